// round 4
// baseline (speedup 1.0000x reference)
#include <cuda_runtime.h>
#include <cuda_bf16.h>
#include <cstdint>

// Problem constants (match reference: BS, DX, DY = 64, 512, 512)
#define BSZ     64
#define DX      512
#define DY      512
#define LTOT    (DX * DY)            // 262144 per batch
#define CHUNK   4096                 // elements per block
#define NCHUNK  (LTOT / CHUNK)       // 64 chunks per batch
#define NTHR    256
#define ITEMS   16                   // CHUNK / NTHR

// Output layout (flattened concatenation of reference tuple, all f32):
//   [0 .. BSZ*LTOT*2)                      : pc (x,y interleaved)
//   [BSZ*LTOT*2 .. BSZ*LTOT*3)             : pc_w
//   [BSZ*LTOT*3 .. BSZ*LTOT*3 + BSZ)       : pc_lens (as float values)
#define W_OFF   ((size_t)BSZ * LTOT * 2)
#define LEN_OFF ((size_t)BSZ * LTOT * 3)

// Scratch (device globals — no allocation allowed)
__device__ int g_counts[BSZ * NCHUNK];
__device__ int g_base[BSZ * NCHUNK];
__device__ int g_lens[BSZ];

// ---------------------------------------------------------------------------
// Kernel 1: per-chunk nonzero count (coalesced float4 reads)
// ---------------------------------------------------------------------------
__global__ __launch_bounds__(NTHR) void k_count(const float* __restrict__ hist) {
    const int b = blockIdx.y, c = blockIdx.x, t = threadIdx.x;
    const float4* p = reinterpret_cast<const float4*>(
        hist + (size_t)b * LTOT + (size_t)c * CHUNK);

    int cnt = 0;
#pragma unroll
    for (int k = 0; k < ITEMS / 4; k++) {            // 4 coalesced float4 loads
        float4 v = __ldg(&p[k * NTHR + t]);
        cnt += (v.x != 0.0f) + (v.y != 0.0f) + (v.z != 0.0f) + (v.w != 0.0f);
    }

    // warp reduce
#pragma unroll
    for (int o = 16; o > 0; o >>= 1)
        cnt += __shfl_down_sync(0xffffffffu, cnt, o);

    __shared__ int s_w[NTHR / 32];
    const int lane = t & 31, wid = t >> 5;
    if (lane == 0) s_w[wid] = cnt;
    __syncthreads();
    if (t == 0) {
        int tot = 0;
#pragma unroll
        for (int i = 0; i < NTHR / 32; i++) tot += s_w[i];
        g_counts[b * NCHUNK + c] = tot;
    }
}

// ---------------------------------------------------------------------------
// Kernel 2: per-batch exclusive scan over NCHUNK=64 counts (1 warp / batch)
// Each lane owns 2 consecutive chunks.
// ---------------------------------------------------------------------------
__global__ void k_scan(float* __restrict__ out) {
    const int b = blockIdx.x, l = threadIdx.x;  // 32 threads
    const int c0 = g_counts[b * NCHUNK + 2 * l];
    const int c1 = g_counts[b * NCHUNK + 2 * l + 1];
    const int s = c0 + c1;
    int incl = s;
#pragma unroll
    for (int o = 1; o < 32; o <<= 1) {
        int n = __shfl_up_sync(0xffffffffu, incl, o);
        if (l >= o) incl += n;
    }
    g_base[b * NCHUNK + 2 * l]     = incl - s;
    g_base[b * NCHUNK + 2 * l + 1] = incl - c1;
    if (l == 31) {
        g_lens[b] = incl;
        out[LEN_OFF + b] = (float)incl;
    }
}

// ---------------------------------------------------------------------------
// Kernel 3: stable compaction scatter. Thread t owns 16 *sequential* elements
// (stability), intra-block exclusive scan, direct compacted writes.
// ---------------------------------------------------------------------------
__global__ __launch_bounds__(NTHR) void k_scatter(
    const float* __restrict__ hist,
    const float* __restrict__ xl,
    const float* __restrict__ yl,
    float* __restrict__ out)
{
    const int b = blockIdx.y, c = blockIdx.x, t = threadIdx.x;

    const float x0  = xl[2 * b];
    const float cxw = (xl[2 * b + 1] - x0) * (1.0f / DX);
    const float y0  = yl[2 * b];
    const float cyw = (yl[2 * b + 1] - y0) * (1.0f / DY);

    const float4* p = reinterpret_cast<const float4*>(
        hist + (size_t)b * LTOT + (size_t)c * CHUNK);

    float v[ITEMS];
#pragma unroll
    for (int k = 0; k < ITEMS / 4; k++) {            // thread-sequential 16 elems
        float4 q = __ldg(&p[t * (ITEMS / 4) + k]);
        v[4 * k + 0] = q.x; v[4 * k + 1] = q.y;
        v[4 * k + 2] = q.z; v[4 * k + 3] = q.w;
    }

    int cnt = 0;
#pragma unroll
    for (int k = 0; k < ITEMS; k++) cnt += (v[k] != 0.0f);

    // block exclusive scan (warp shfl scan + serial cross-warp)
    const int lane = t & 31, wid = t >> 5;
    int incl = cnt;
#pragma unroll
    for (int o = 1; o < 32; o <<= 1) {
        int n = __shfl_up_sync(0xffffffffu, incl, o);
        if (lane >= o) incl += n;
    }
    __shared__ int s_w[NTHR / 32];
    __shared__ int s_off[NTHR / 32];
    if (lane == 31) s_w[wid] = incl;
    __syncthreads();
    if (t == 0) {
        int run = 0;
#pragma unroll
        for (int i = 0; i < NTHR / 32; i++) { s_off[i] = run; run += s_w[i]; }
    }
    __syncthreads();

    int pos = g_base[b * NCHUNK + c] + s_off[wid] + (incl - cnt);

    float2* pc = reinterpret_cast<float2*>(out) + (size_t)b * LTOT;
    float*  pw = out + W_OFF + (size_t)b * LTOT;

    const int lin0 = c * CHUNK + t * ITEMS;
#pragma unroll
    for (int k = 0; k < ITEMS; k++) {
        if (v[k] != 0.0f) {
            const int lin = lin0 + k;
            const int i = lin >> 9;       // / DY
            const int j = lin & (DY - 1); // % DY
            float2 xy;
            xy.x = x0 + cxw * ((float)i + 0.5f);
            xy.y = y0 + cyw * ((float)j + 0.5f);
            pc[pos] = xy;
            pw[pos] = v[k];
            pos++;
        }
    }
}

// ---------------------------------------------------------------------------
// Kernel 4: zero the tail [lens[b], LTOT). Blocks fully inside the compacted
// region exit after one uniform load. Coalesced stride pattern.
// ---------------------------------------------------------------------------
__global__ __launch_bounds__(NTHR) void k_tail(float* __restrict__ out) {
    const int b = blockIdx.y, c = blockIdx.x, t = threadIdx.x;
    const int lens = g_lens[b];
    const int start = c * CHUNK;
    if (start + CHUNK <= lens) return;

    float2* pc = reinterpret_cast<float2*>(out) + (size_t)b * LTOT;
    float*  pw = out + W_OFF + (size_t)b * LTOT;

#pragma unroll
    for (int k = 0; k < ITEMS; k++) {
        const int pos = start + k * NTHR + t;
        if (pos >= lens) {
            pc[pos] = make_float2(0.0f, 0.0f);
            pw[pos] = 0.0f;
        }
    }
}

// ---------------------------------------------------------------------------
extern "C" void kernel_launch(void* const* d_in, const int* in_sizes, int n_in,
                              void* d_out, int out_size)
{
    const float* hist = (const float*)d_in[0];
    const float* xl   = (const float*)d_in[1];
    const float* yl   = (const float*)d_in[2];
    float* out        = (float*)d_out;

    dim3 grid(NCHUNK, BSZ);
    k_count  <<<grid, NTHR>>>(hist);
    k_scan   <<<BSZ, 32>>>(out);
    k_scatter<<<grid, NTHR>>>(hist, xl, yl, out);
    k_tail   <<<grid, NTHR>>>(out);
}

// round 6
// speedup vs baseline: 2.5056x; 2.5056x over previous
#include <cuda_runtime.h>
#include <cuda_bf16.h>
#include <cstdint>

// Problem constants (match reference: BS, DX, DY = 64, 512, 512)
#define BSZ     64
#define DX      512
#define DY      512
#define LTOT    (DX * DY)            // 262144 per batch
#define CHUNK   4096                 // elements per block
#define NCHUNK  (LTOT / CHUNK)       // 64 chunks per batch
#define NTHR    256
#define ITEMS   16                   // CHUNK / NTHR

// Output layout (flattened concatenation of reference tuple, all f32):
//   [0 .. BSZ*LTOT*2)                      : pc (x,y interleaved)
//   [BSZ*LTOT*2 .. BSZ*LTOT*3)             : pc_w
//   [BSZ*LTOT*3 .. BSZ*LTOT*3 + BSZ)       : pc_lens (as float values)
#define W_OFF   ((size_t)BSZ * LTOT * 2)
#define LEN_OFF ((size_t)BSZ * LTOT * 3)

// Scratch (device globals — no allocation allowed)
__device__ int g_counts[BSZ * NCHUNK];
__device__ int g_base[BSZ * NCHUNK];
__device__ int g_lens[BSZ];

// ---------------------------------------------------------------------------
// Kernel 1: per-chunk nonzero count (coalesced float4 reads)
// ---------------------------------------------------------------------------
__global__ __launch_bounds__(NTHR) void k_count(const float* __restrict__ hist) {
    const int b = blockIdx.y, c = blockIdx.x, t = threadIdx.x;
    const float4* p = reinterpret_cast<const float4*>(
        hist + (size_t)b * LTOT + (size_t)c * CHUNK);

    int cnt = 0;
#pragma unroll
    for (int k = 0; k < ITEMS / 4; k++) {            // 4 coalesced float4 loads
        float4 v = __ldg(&p[k * NTHR + t]);
        cnt += (v.x != 0.0f) + (v.y != 0.0f) + (v.z != 0.0f) + (v.w != 0.0f);
    }

    // warp reduce
#pragma unroll
    for (int o = 16; o > 0; o >>= 1)
        cnt += __shfl_down_sync(0xffffffffu, cnt, o);

    __shared__ int s_w[NTHR / 32];
    const int lane = t & 31, wid = t >> 5;
    if (lane == 0) s_w[wid] = cnt;
    __syncthreads();
    if (t == 0) {
        int tot = 0;
#pragma unroll
        for (int i = 0; i < NTHR / 32; i++) tot += s_w[i];
        g_counts[b * NCHUNK + c] = tot;
    }
}

// ---------------------------------------------------------------------------
// Kernel 2: per-batch exclusive scan over NCHUNK=64 counts (1 warp / batch)
// Each lane owns 2 consecutive chunks.
// ---------------------------------------------------------------------------
__global__ void k_scan(float* __restrict__ out) {
    const int b = blockIdx.x, l = threadIdx.x;  // 32 threads
    const int c0 = g_counts[b * NCHUNK + 2 * l];
    const int c1 = g_counts[b * NCHUNK + 2 * l + 1];
    const int s = c0 + c1;
    int incl = s;
#pragma unroll
    for (int o = 1; o < 32; o <<= 1) {
        int n = __shfl_up_sync(0xffffffffu, incl, o);
        if (l >= o) incl += n;
    }
    g_base[b * NCHUNK + 2 * l]     = incl - s;
    g_base[b * NCHUNK + 2 * l + 1] = incl - c1;
    if (l == 31) {
        g_lens[b] = incl;
        out[LEN_OFF + b] = (float)incl;
    }
}

// ---------------------------------------------------------------------------
// Kernel 3: stable compaction scatter with SMEM staging + fused tail zero.
//   Phase A: thread t owns 16 *sequential* elements (stability), block-wide
//            exclusive scan, scatter (lin,val) pairs into shared memory.
//   Phase B: coalesced emit of float2 xy (recomputed from lin) and w.
//   Phase C: zero this chunk's slice of the tail region [lens, LTOT).
// ---------------------------------------------------------------------------
__global__ __launch_bounds__(NTHR) void k_scatter(
    const float* __restrict__ hist,
    const float* __restrict__ xl,
    const float* __restrict__ yl,
    float* __restrict__ out)
{
    const int b = blockIdx.y, c = blockIdx.x, t = threadIdx.x;

    __shared__ int   s_idx[CHUNK];      // 16 KB
    __shared__ float s_val[CHUNK];      // 16 KB
    __shared__ int   s_woff[NTHR / 32];
    __shared__ int   s_tot;

    const float x0  = xl[2 * b];
    const float cxw = (xl[2 * b + 1] - x0) * (1.0f / DX);
    const float y0  = yl[2 * b];
    const float cyw = (yl[2 * b + 1] - y0) * (1.0f / DY);

    const float4* p = reinterpret_cast<const float4*>(
        hist + (size_t)b * LTOT + (size_t)c * CHUNK);

    float v[ITEMS];
#pragma unroll
    for (int k = 0; k < ITEMS / 4; k++) {            // thread-sequential 16 elems
        float4 q = __ldg(&p[t * (ITEMS / 4) + k]);
        v[4 * k + 0] = q.x; v[4 * k + 1] = q.y;
        v[4 * k + 2] = q.z; v[4 * k + 3] = q.w;
    }

    int cnt = 0;
#pragma unroll
    for (int k = 0; k < ITEMS; k++) cnt += (v[k] != 0.0f);

    // block exclusive scan (warp shfl scan + serial cross-warp)
    const int lane = t & 31, wid = t >> 5;
    int incl = cnt;
#pragma unroll
    for (int o = 1; o < 32; o <<= 1) {
        int n = __shfl_up_sync(0xffffffffu, incl, o);
        if (lane >= o) incl += n;
    }
    __shared__ int s_wsum[NTHR / 32];
    if (lane == 31) s_wsum[wid] = incl;
    __syncthreads();
    if (t == 0) {
        int run = 0;
#pragma unroll
        for (int i = 0; i < NTHR / 32; i++) { s_woff[i] = run; run += s_wsum[i]; }
        s_tot = run;
    }
    __syncthreads();

    // Phase A: scatter into SMEM at local compacted positions
    int lp = s_woff[wid] + (incl - cnt);
    const int lin0 = c * CHUNK + t * ITEMS;
#pragma unroll
    for (int k = 0; k < ITEMS; k++) {
        if (v[k] != 0.0f) {
            s_idx[lp] = lin0 + k;
            s_val[lp] = v[k];
            lp++;
        }
    }
    __syncthreads();

    // Phase B: fully coalesced emit
    const int total = s_tot;
    const int base  = g_base[b * NCHUNK + c];
    float2* pc = reinterpret_cast<float2*>(out) + (size_t)b * LTOT;
    float*  pw = out + W_OFF + (size_t)b * LTOT;

    for (int s = t; s < total; s += NTHR) {
        const int lin = s_idx[s];
        const int i = lin >> 9;       // / DY
        const int j = lin & (DY - 1); // % DY
        float2 xy;
        xy.x = x0 + cxw * ((float)i + 0.5f);
        xy.y = y0 + cyw * ((float)j + 0.5f);
        pc[base + s] = xy;
        pw[base + s] = s_val[s];
    }

    // Phase C: fused tail zero for this chunk's output slice
    const int lens  = g_lens[b];
    const int start = c * CHUNK;
    const int zbeg  = (lens > start) ? lens : start;
    const int zend  = start + CHUNK;
    for (int s = zbeg + t; s < zend; s += NTHR) {
        pc[s] = make_float2(0.0f, 0.0f);
        pw[s] = 0.0f;
    }
}

// ---------------------------------------------------------------------------
extern "C" void kernel_launch(void* const* d_in, const int* in_sizes, int n_in,
                              void* d_out, int out_size)
{
    const float* hist = (const float*)d_in[0];
    const float* xl   = (const float*)d_in[1];
    const float* yl   = (const float*)d_in[2];
    float* out        = (float*)d_out;

    dim3 grid(NCHUNK, BSZ);
    k_count  <<<grid, NTHR>>>(hist);
    k_scan   <<<BSZ, 32>>>(out);
    k_scatter<<<grid, NTHR>>>(hist, xl, yl, out);
}